// round 15
// baseline (speedup 1.0000x reference)
#include <cuda_runtime.h>
#include <cuda_fp16.h>
#include <cstdint>

#define Bb 8
#define Ss 25
#define Hh 512
#define Ww 512
#define Aa 20
#define Kk 100
#define NMAPS (Bb*Ss)        // 200
#define HWs (Hh*Ww)          // 262144
#define LSEG 64              // slots per LANE segment (max maxima per lane strip)
#define NLANESEG 2048        // 64 warps * 32 lanes per map
#define CAP (NLANESEG*LSEG)  // 131072

#define OFF_SCORES 0
#define OFF_COORDS 20000
#define OFF_VALID  60000
#define OFF_EPAF   80000
#define OFF_ER     1680000
#define OFF_PV     3280000
#define OFF_IP     4880000

typedef unsigned long long ull;

__device__ float2 g_part[NMAPS*8];
__device__ float g_m[NMAPS];
__device__ float g_Z[NMAPS];
__device__ ull   g_cutkey[NMAPS];
__device__ int   g_bcnt[NMAPS*NLANESEG];
__device__ ull   g_cand[(size_t)NMAPS*CAP];
__device__ int g_selx[NMAPS*Kk];
__device__ int g_sely[NMAPS*Kk];
__device__ int g_selv[NMAPS*Kk];

__device__ __forceinline__ unsigned h2ex2(unsigned a) {
    unsigned r; asm("ex2.approx.f16x2 %0,%1;" : "=r"(r) : "r"(a)); return r;
}
__device__ __forceinline__ unsigned hadd2u(unsigned a, unsigned b) {
    unsigned r; asm("add.rn.f16x2 %0,%1,%2;" : "=r"(r) : "r"(a), "r"(b)); return r;
}
__device__ __forceinline__ unsigned pack_h2(float lo, float hi) {
    unsigned r; asm("cvt.rn.f16x2.f32 %0,%1,%2;" : "=r"(r) : "f"(hi), "f"(lo)); return r;
}

// ---------------------------------------------------------------------------
// Kernel 1 (fused): ONE pose_map pass per map (R10 structure: 32-row strips,
// batched 4-row register loads). Candidate emission is LANE-PRIVATE: each
// lane owns a 64-slot gmem segment, so no ballot/popc/min cross-lane ops in
// the hot loop (max 2 maxima per 4-px group per row x 32 rows = 64, exact).
// ---------------------------------------------------------------------------
__global__ void __launch_bounds__(256) k_fused(const float* __restrict__ pose) {
    int map = blockIdx.y;
    int tid = threadIdx.x;
    int wrp = tid >> 5, lane = tid & 31;
    int wg = blockIdx.x * 8 + wrp;        // 64 warps per map
    int seg = wg & 3;                     // column segment [0,4)
    int strip = wg >> 2;                  // row strip [0,16)
    int C0 = seg * 128;
    int R0 = strip * 32;
    const float* pm = pose + (size_t)map*HWs;

    __shared__ float sm[8], ss[8];

    const float NEG = -3.4e38f;
    const float L2E = 1.4426950408889634f;
    int xc = C0 + lane*4;
    bool hval = (lane == 0) ? (C0 > 0) : ((lane == 31) ? (C0 + 128 < Ww) : false);
    int hx = (lane == 0) ? (C0 - 1) : (C0 + 128);

    ull* wdst = g_cand + (size_t)map*CAP + (size_t)(wg*32 + lane)*LSEG;
    int wcnt = 0;

    float4 A, B, m01;
    float hA = NEG, hB = NEG, haM = NEG;
    {
        float4 t; float hT = NEG;
        if (R0 > 0) {
            t = *(const float4*)(pm + (size_t)(R0-1)*Ww + xc);
            if (hval) hT = __ldg(pm + (size_t)(R0-1)*Ww + hx);
        } else t = make_float4(NEG, NEG, NEG, NEG);
        A = *(const float4*)(pm + (size_t)R0*Ww + xc);
        if (hval) hA = __ldg(pm + (size_t)R0*Ww + hx);
        B = *(const float4*)(pm + (size_t)(R0+1)*Ww + xc);
        if (hval) hB = __ldg(pm + (size_t)(R0+1)*Ww + hx);
        m01 = make_float4(fmaxf(t.x,A.x), fmaxf(t.y,A.y), fmaxf(t.z,A.z), fmaxf(t.w,A.w));
        haM = fmaxf(hT, hA);
    }

    float mx = NEG;
    float s = 0.f;
    for (int c8 = 0; c8 < 4; c8++) {
        unsigned acc0 = 0u, acc1 = 0u;
#pragma unroll
        for (int b = 0; b < 2; b++) {
            int yc0 = R0 + c8*8 + b*4;
            float4 Rr[4]; float hR[4];
#pragma unroll
            for (int j = 0; j < 4; j++) {
                int yp = yc0 + 2 + j;
                if (yp < Hh) {
                    Rr[j] = *(const float4*)(pm + (size_t)yp*Ww + xc);
                    hR[j] = NEG;
                    if (hval) hR[j] = __ldg(pm + (size_t)yp*Ww + hx);
                } else {
                    Rr[j] = make_float4(NEG, NEG, NEG, NEG);
                    hR[j] = NEG;
                }
            }
#pragma unroll
            for (int j = 0; j < 4; j++) {
                int yc = yc0 + j;
                mx = fmaxf(fmaxf(mx, fmaxf(A.x,A.y)), fmaxf(A.z,A.w));
                acc0 = hadd2u(acc0, h2ex2(pack_h2(A.x*L2E, A.y*L2E)));
                acc1 = hadd2u(acc1, h2ex2(pack_h2(A.z*L2E, A.w*L2E)));
                float4 vm = make_float4(fmaxf(m01.x,B.x), fmaxf(m01.y,B.y),
                                        fmaxf(m01.z,B.z), fmaxf(m01.w,B.w));
                float hvm = fmaxf(haM, hB);
                float fromL = __shfl_up_sync(0xFFFFFFFFu, vm.w, 1);
                if (lane == 0) fromL = hvm;
                float fromR = __shfl_down_sync(0xFFFFFFFFu, vm.x, 1);
                if (lane == 31) fromR = hvm;
                float p01 = fmaxf(vm.x, vm.y);
                float p12 = fmaxf(vm.y, vm.z);
                float p23 = fmaxf(vm.z, vm.w);
                float hv[4];
                hv[0] = fmaxf(fromL, p01);
                hv[1] = fmaxf(p01, vm.z);
                hv[2] = fmaxf(p12, vm.w);
                hv[3] = fmaxf(p23, fromR);
                float av[4] = {A.x, A.y, A.z, A.w};
#pragma unroll
                for (int k = 0; k < 4; k++) {
                    if (av[k] == hv[k]) {              // 3x3 local max
                        unsigned u = __float_as_uint(av[k]);
                        unsigned ord = u ^ ((u >> 31) ? 0xFFFFFFFFu : 0x80000000u);
                        if (wcnt < LSEG)
                            wdst[wcnt] = ((ull)(~ord) << 32) | (unsigned)(yc*Ww + xc + k);
                        wcnt++;
                    }
                }
                m01 = make_float4(fmaxf(A.x,B.x), fmaxf(A.y,B.y),
                                  fmaxf(A.z,B.z), fmaxf(A.w,B.w));
                A = B; B = Rr[j];
                haM = fmaxf(hA, hB); hA = hB; hB = hR[j];
            }
        }
        __half2 hh0 = *(__half2*)&acc0, hh1 = *(__half2*)&acc1;
        float2 f0 = __half22float2(hh0), f1 = __half22float2(hh1);
        s += (f0.x + f0.y) + (f1.x + f1.y);
    }
    g_bcnt[map*NLANESEG + wg*32 + lane] = min(wcnt, LSEG);

    for (int o = 16; o; o >>= 1) {
        mx = fmaxf(mx, __shfl_down_sync(0xFFFFFFFFu, mx, o));
        s += __shfl_down_sync(0xFFFFFFFFu, s, o);
    }
    if (lane == 0) { sm[wrp] = mx; ss[wrp] = s; }
    __syncthreads();
    if (tid < 8) {
        mx = sm[tid]; s = ss[tid];
        for (int o = 4; o; o >>= 1) {
            mx = fmaxf(mx, __shfl_down_sync(0xFFu, mx, o));
            s += __shfl_down_sync(0xFFu, s, o);
        }
        if (tid == 0) g_part[map*8 + blockIdx.x] = make_float2(mx, s);
    }
}

// ---------------------------------------------------------------------------
// Kernel 2: finalize m, Z, logit cutoff -> key-space threshold
// ---------------------------------------------------------------------------
__global__ void k_finalize() {
    int map = threadIdx.x;
    if (map >= NMAPS) return;
    float m = -3.4e38f, S0 = 0.f;
#pragma unroll
    for (int i = 0; i < 8; i++) {
        float2 p = g_part[map*8 + i];
        m = fmaxf(m, p.x);
        S0 += p.y;
    }
    float Z = S0 * __expf(-m);
    g_m[map] = m; g_Z[map] = Z;
    float cut = m + fmaxf(__logf(Z * (2.0f / (float)HWs)), -4.6051702f);
    unsigned u = __float_as_uint(cut);
    unsigned ord = u ^ ((u >> 31) ? 0xFFFFFFFFu : 0x80000000u);
    g_cutkey[map] = ((ull)(~ord)) << 32;
}

// ---------------------------------------------------------------------------
// Kernel 3: exact top-K over cut-filtered candidates (512 threads).
// 2048 lane-segments/map; predicated iteration (i&63) < bcnt[i>>6].
// ---------------------------------------------------------------------------
__global__ void __launch_bounds__(512) k_topk(float* __restrict__ out) {
    int map = blockIdx.x;
    int tid = threadIdx.x;
    const ull* cand = g_cand + (size_t)map*CAP;
    ull cutkey = g_cutkey[map];

    __shared__ int bcnt[NLANESEG];
    __shared__ int hist[4096];
    __shared__ int psum[256];
    __shared__ ull list[2048];
    __shared__ int sh_T, sh_C, sh_H, nlist, sh_tot;
    __shared__ int sh_mode;

    for (int i = tid; i < NLANESEG; i += 512) bcnt[i] = g_bcnt[map*NLANESEG + i];
    for (int i = tid; i < 4096; i += 512) hist[i] = 0;
    if (tid == 0) { sh_mode = 0; nlist = 0; }
    __syncthreads();

#pragma unroll 4
    for (int i = tid; i < CAP; i += 512) {
        if ((i & (LSEG-1)) < bcnt[i >> 6]) {
            ull key = __ldg(cand + i);
            if (key < cutkey) atomicAdd(&hist[(int)(key >> 52)], 1);
        }
    }
    __syncthreads();
    if (tid < 256) {
        int sg = 0;
        for (int j = 0; j < 16; j++) sg += hist[tid*16 + j];
        psum[tid] = sg;
    }
    __syncthreads();
    if (tid == 0) {
        int run = 0;
        for (int t = 0; t < 256; t++) { int tmp = psum[t]; psum[t] = run; run += tmp; }
        sh_tot = run;
    }
    __syncthreads();
    int ntot = sh_tot;

    unsigned thr24 = 0;
    int T12 = 0;
    if (ntot > Kk) {
        if (tid < 256) {
            int c = psum[tid];
            int hi = 0;
            for (int j = 0; j < 16; j++) hi += hist[tid*16 + j];
            if (c < Kk && c + hi >= Kk) {
                int cc = c;
                for (int j = 0; j < 16; j++) {
                    int h = hist[tid*16 + j];
                    if (cc + h >= Kk) { sh_T = tid*16 + j; sh_C = cc; sh_H = h; break; }
                    cc += h;
                }
            }
        }
        __syncthreads();
        int T = sh_T, C0 = sh_C, HT = sh_H;
        if (C0 + HT <= 2048) {
            if (tid == 0) sh_mode = 1;
            T12 = T;
        } else {
            __syncthreads();
            for (int i = tid; i < 4096; i += 512) hist[i] = 0;
            __syncthreads();
            for (int i = tid; i < CAP; i += 512) {
                if ((i & (LSEG-1)) < bcnt[i >> 6]) {
                    ull key = __ldg(cand + i);
                    if (key < cutkey && (int)(key >> 52) == T)
                        atomicAdd(&hist[(int)((key >> 40) & 0xFFF)], 1);
                }
            }
            __syncthreads();
            int need = Kk - C0;
            if (tid < 256) {
                int sg = 0;
                for (int j = 0; j < 16; j++) sg += hist[tid*16 + j];
                psum[tid] = sg;
            }
            __syncthreads();
            if (tid == 0) { int run = 0; for (int t = 0; t < 256; t++) { int tmp = psum[t]; psum[t] = run; run += tmp; } }
            __syncthreads();
            if (tid < 256) {
                int c = psum[tid];
                int hi = 0;
                for (int j = 0; j < 16; j++) hi += hist[tid*16 + j];
                if (c < need && c + hi >= need) {
                    int cc = c;
                    for (int j = 0; j < 16; j++) {
                        int h = hist[tid*16 + j];
                        if (cc + h >= need) { sh_T = tid*16 + j; break; }
                        cc += h;
                    }
                }
            }
            if (tid == 0) sh_mode = 2;
            __syncthreads();
            thr24 = ((unsigned)T << 12) | (unsigned)sh_T;
            T12 = T;
        }
    }
    __syncthreads();
    int mode = sh_mode;

#pragma unroll 4
    for (int i = tid; i < CAP; i += 512) {
        if ((i & (LSEG-1)) < bcnt[i >> 6]) {
            ull key = __ldg(cand + i);
            if (key >= cutkey) continue;
            bool keep;
            if (mode == 0)      keep = true;
            else if (mode == 1) keep = ((int)(key >> 52) <= T12);
            else                keep = ((unsigned)(key >> 40) <= thr24);
            if (keep) {
                int p = atomicAdd(&nlist, 1);
                if (p < 2048) list[p] = key;
            }
        }
    }
    __syncthreads();
    int M = min(nlist, 2048);
    float m = g_m[map];
    float invZ = 1.f / g_Z[map];

    for (int t = tid; t < M; t += 512) {
        ull k = list[t];
        int rank = 0;
        for (int j = 0; j < M; j++) rank += (list[j] < k);
        if (rank < Kk) {
            unsigned idx = (unsigned)(k & 0xFFFFFFFFu);
            int gx = idx & 511, gy = idx >> 9;
            unsigned ord = ~(unsigned)(k >> 32);
            unsigned u = (ord & 0x80000000u) ? (ord ^ 0x80000000u) : ~ord;
            float v = __uint_as_float(u);
            float sc = __expf(v - m) * invZ;
            int o = map*Kk + rank;
            out[OFF_SCORES + o]       = sc;
            out[OFF_COORDS + o*2]     = (float)gx;
            out[OFF_COORDS + o*2 + 1] = (float)gy;
            out[OFF_VALID  + o]       = 1.f;
            g_selx[o] = gx; g_sely[o] = gy; g_selv[o] = 1;
        }
    }
    if (tid >= M && tid < Kk) {
        int o = map*Kk + tid;
        out[OFF_SCORES + o]       = 0.f;
        out[OFF_COORDS + o*2]     = 0.f;
        out[OFF_COORDS + o*2 + 1] = 0.f;
        out[OFF_VALID  + o]       = 0.f;
        g_selx[o] = 0; g_sely[o] = 0; g_selv[o] = 0;
    }
}

// ---------------------------------------------------------------------------
// Kernel 4: KxK pair edges. grid (40, B*A).
// ---------------------------------------------------------------------------
__global__ void __launch_bounds__(256) k_pairs(const float* __restrict__ paf,
                                               float* __restrict__ out) {
    int ba = blockIdx.y;
    int a  = ba % Aa;
    int b  = ba / Aa;
    int m1 = b*Ss + a, m2 = m1 + 1;
    __shared__ int x1[Kk], y1[Kk], v1[Kk], x2[Kk], y2[Kk], v2[Kk];
    int tid = threadIdx.x;
    if (tid < Kk) {
        x1[tid] = g_selx[m1*Kk + tid]; y1[tid] = g_sely[m1*Kk + tid]; v1[tid] = g_selv[m1*Kk + tid];
        x2[tid] = g_selx[m2*Kk + tid]; y2[tid] = g_sely[m2*Kk + tid]; v2[tid] = g_selv[m2*Kk + tid];
    }
    __syncthreads();
    int idx = blockIdx.x * 256 + tid;
    if (idx >= Kk*Kk) return;
    const float* pafx = paf + (size_t)(ba*2)*HWs;
    const float* pafy = pafx + HWs;
    size_t eb = (size_t)ba * Kk * Kk;
    size_t ib = (size_t)ba * 2 * Kk * Kk;
    int j2 = idx / Kk, j1 = idx - j2*Kk;
    float dx = (float)(x2[j2] - x1[j1]);
    float dy = (float)(y2[j2] - y1[j1]);
    float R = sqrtf(dx*dx + dy*dy);
    bool pv = (R < 20.0f) && v1[j1] && v2[j2];
    float li = 0.f;
    if (pv && R > 0.f) {
        float tvx = dx / R, tvy = dy / R;
        int px1 = x1[j1], py1 = y1[j1], px2 = x2[j2], py2 = y2[j2];
        float acc = 0.f;
#pragma unroll
        for (int t = 0; t < 10; t++) {
            int sx = (px1*(9 - t) + px2*t) / 9;
            int sy = (py1*(9 - t) + py2*t) / 9;
            int off = sy*Ww + sx;
            acc += tvx*__ldg(pafx + off) + tvy*__ldg(pafy + off);
        }
        li = acc * 0.1f;
    }
    out[OFF_EPAF + eb + idx] = li;
    out[OFF_ER   + eb + idx] = pv ? R : 0.f;
    out[OFF_PV   + eb + idx] = pv ? 1.f : 0.f;
    out[OFF_IP   + ib + idx]           = (float)(a*Kk + j1);
    out[OFF_IP   + ib + Kk*Kk + idx]   = (float)((a + 1)*Kk + j2);
}

extern "C" void kernel_launch(void* const* d_in, const int* in_sizes, int n_in,
                              void* d_out, int out_size) {
    const float* pose = (const float*)d_in[0];
    const float* paf  = (const float*)d_in[1];
    float* out = (float*)d_out;
    k_fused   <<<dim3(8, NMAPS), 256>>>(pose);
    k_finalize<<<1, 256>>>();
    k_topk    <<<NMAPS, 512>>>(out);
    k_pairs   <<<dim3((Kk*Kk + 255)/256, Bb*Aa), 256>>>(paf, out);
}

// round 16
// speedup vs baseline: 2.2266x; 2.2266x over previous
#include <cuda_runtime.h>
#include <cuda_fp16.h>
#include <cstdint>

#define Bb 8
#define Ss 25
#define Hh 512
#define Ww 512
#define Aa 20
#define Kk 100
#define NMAPS (Bb*Ss)        // 200
#define HWs (Hh*Ww)          // 262144
#define CAP 65536            // 64 warps/map * 1024-slot warp segments
#define WSEG 1024

#define OFF_SCORES 0
#define OFF_COORDS 20000
#define OFF_VALID  60000
#define OFF_EPAF   80000
#define OFF_ER     1680000
#define OFF_PV     3280000
#define OFF_IP     4880000

typedef unsigned long long ull;

__device__ float2 g_part[NMAPS*8];
__device__ int   g_bcnt[NMAPS*64];
__device__ ull   g_cand[(size_t)NMAPS*CAP];
__device__ int g_selx[NMAPS*Kk];
__device__ int g_sely[NMAPS*Kk];
__device__ int g_selv[NMAPS*Kk];

__device__ __forceinline__ unsigned h2ex2(unsigned a) {
    unsigned r; asm("ex2.approx.f16x2 %0,%1;" : "=r"(r) : "r"(a)); return r;
}
__device__ __forceinline__ unsigned hadd2u(unsigned a, unsigned b) {
    unsigned r; asm("add.rn.f16x2 %0,%1,%2;" : "=r"(r) : "r"(a), "r"(b)); return r;
}
__device__ __forceinline__ unsigned pack_h2(float lo, float hi) {
    unsigned r; asm("cvt.rn.f16x2.f32 %0,%1,%2;" : "=r"(r) : "f"(hi), "f"(lo)); return r;
}

// ---------------------------------------------------------------------------
// Kernel 1 (fused): ONE pose_map pass per map (R10-proven config).
// 32-row strips, batched 4-row register loads, warp-ballot emission.
// ---------------------------------------------------------------------------
__global__ void __launch_bounds__(256) k_fused(const float* __restrict__ pose) {
    int map = blockIdx.y;
    int tid = threadIdx.x;
    int wrp = tid >> 5, lane = tid & 31;
    int wg = blockIdx.x * 8 + wrp;        // 64 warps per map
    int seg = wg & 3;                     // column segment [0,4)
    int strip = wg >> 2;                  // row strip [0,16)
    int C0 = seg * 128;
    int R0 = strip * 32;
    const float* pm = pose + (size_t)map*HWs;

    __shared__ float sm[8], ss[8];

    const float NEG = -3.4e38f;
    const float L2E = 1.4426950408889634f;
    int xc = C0 + lane*4;
    bool hval = (lane == 0) ? (C0 > 0) : ((lane == 31) ? (C0 + 128 < Ww) : false);
    int hx = (lane == 0) ? (C0 - 1) : (C0 + 128);

    ull* wdst = g_cand + (size_t)map*CAP + (size_t)wg*WSEG;
    int wcnt = 0;

    float4 A, B, m01;
    float hA = NEG, hB = NEG, haM = NEG;
    {
        float4 t; float hT = NEG;
        if (R0 > 0) {
            t = *(const float4*)(pm + (size_t)(R0-1)*Ww + xc);
            if (hval) hT = __ldg(pm + (size_t)(R0-1)*Ww + hx);
        } else t = make_float4(NEG, NEG, NEG, NEG);
        A = *(const float4*)(pm + (size_t)R0*Ww + xc);
        if (hval) hA = __ldg(pm + (size_t)R0*Ww + hx);
        B = *(const float4*)(pm + (size_t)(R0+1)*Ww + xc);
        if (hval) hB = __ldg(pm + (size_t)(R0+1)*Ww + hx);
        m01 = make_float4(fmaxf(t.x,A.x), fmaxf(t.y,A.y), fmaxf(t.z,A.z), fmaxf(t.w,A.w));
        haM = fmaxf(hT, hA);
    }

    float mx = NEG;
    float s = 0.f;
    for (int c8 = 0; c8 < 4; c8++) {
        unsigned acc0 = 0u, acc1 = 0u;
#pragma unroll
        for (int b = 0; b < 2; b++) {
            int yc0 = R0 + c8*8 + b*4;
            float4 Rr[4]; float hR[4];
#pragma unroll
            for (int j = 0; j < 4; j++) {
                int yp = yc0 + 2 + j;
                if (yp < Hh) {
                    Rr[j] = *(const float4*)(pm + (size_t)yp*Ww + xc);
                    hR[j] = NEG;
                    if (hval) hR[j] = __ldg(pm + (size_t)yp*Ww + hx);
                } else {
                    Rr[j] = make_float4(NEG, NEG, NEG, NEG);
                    hR[j] = NEG;
                }
            }
#pragma unroll
            for (int j = 0; j < 4; j++) {
                int yc = yc0 + j;
                mx = fmaxf(fmaxf(mx, fmaxf(A.x,A.y)), fmaxf(A.z,A.w));
                acc0 = hadd2u(acc0, h2ex2(pack_h2(A.x*L2E, A.y*L2E)));
                acc1 = hadd2u(acc1, h2ex2(pack_h2(A.z*L2E, A.w*L2E)));
                float4 vm = make_float4(fmaxf(m01.x,B.x), fmaxf(m01.y,B.y),
                                        fmaxf(m01.z,B.z), fmaxf(m01.w,B.w));
                float hvm = fmaxf(haM, hB);
                float fromL = __shfl_up_sync(0xFFFFFFFFu, vm.w, 1);
                if (lane == 0) fromL = hvm;
                float fromR = __shfl_down_sync(0xFFFFFFFFu, vm.x, 1);
                if (lane == 31) fromR = hvm;
                float p01 = fmaxf(vm.x, vm.y);
                float p12 = fmaxf(vm.y, vm.z);
                float p23 = fmaxf(vm.z, vm.w);
                float hv[4];
                hv[0] = fmaxf(fromL, p01);
                hv[1] = fmaxf(p01, vm.z);
                hv[2] = fmaxf(p12, vm.w);
                hv[3] = fmaxf(p23, fromR);
                float av[4] = {A.x, A.y, A.z, A.w};
#pragma unroll
                for (int k = 0; k < 4; k++) {
                    bool isc = (av[k] == hv[k]);
                    unsigned mask = __ballot_sync(0xFFFFFFFFu, isc);
                    if (isc) {
                        unsigned u = __float_as_uint(av[k]);
                        unsigned ord = u ^ ((u >> 31) ? 0xFFFFFFFFu : 0x80000000u);
                        int off = wcnt + __popc(mask & ((1u << lane) - 1u));
                        if (off < WSEG)
                            wdst[off] = ((ull)(~ord) << 32) | (unsigned)(yc*Ww + xc + k);
                    }
                    wcnt = min(wcnt + __popc(mask), WSEG);
                }
                m01 = make_float4(fmaxf(A.x,B.x), fmaxf(A.y,B.y),
                                  fmaxf(A.z,B.z), fmaxf(A.w,B.w));
                A = B; B = Rr[j];
                haM = fmaxf(hA, hB); hA = hB; hB = hR[j];
            }
        }
        __half2 hh0 = *(__half2*)&acc0, hh1 = *(__half2*)&acc1;
        float2 f0 = __half22float2(hh0), f1 = __half22float2(hh1);
        s += (f0.x + f0.y) + (f1.x + f1.y);
    }
    if (lane == 0) g_bcnt[map*64 + wg] = wcnt;

    for (int o = 16; o; o >>= 1) {
        mx = fmaxf(mx, __shfl_down_sync(0xFFFFFFFFu, mx, o));
        s += __shfl_down_sync(0xFFFFFFFFu, s, o);
    }
    if (lane == 0) { sm[wrp] = mx; ss[wrp] = s; }
    __syncthreads();
    if (tid < 8) {
        mx = sm[tid]; s = ss[tid];
        for (int o = 4; o; o >>= 1) {
            mx = fmaxf(mx, __shfl_down_sync(0xFFu, mx, o));
            s += __shfl_down_sync(0xFFu, s, o);
        }
        if (tid == 0) g_part[map*8 + blockIdx.x] = make_float2(mx, s);
    }
}

// ---------------------------------------------------------------------------
// Kernel 2: exact top-K (512 threads). Finalize (m, Z, cutkey) is computed
// in-block from g_part — no separate single-block finalize kernel.
// Radix round 1 with round-2 fallback, compact, rank-scatter.
// ---------------------------------------------------------------------------
__global__ void __launch_bounds__(512) k_topk(float* __restrict__ out) {
    int map = blockIdx.x;
    int tid = threadIdx.x;
    const ull* cand = g_cand + (size_t)map*CAP;

    __shared__ int bcnt[64];
    __shared__ int hist[4096];
    __shared__ int psum[256];
    __shared__ ull list[2048];
    __shared__ int sh_T, sh_C, sh_H, nlist, sh_tot;
    __shared__ int sh_mode;
    __shared__ float sh_m, sh_invZ;
    __shared__ ull sh_cutkey;

    if (tid < 64) bcnt[tid] = g_bcnt[map*64 + tid];
    for (int i = tid; i < 4096; i += 512) hist[i] = 0;
    if (tid == 0) {
        sh_mode = 0; nlist = 0;
        // in-block finalize: m, Z, cut -> key-space threshold
        float m = -3.4e38f, S0 = 0.f;
#pragma unroll
        for (int i = 0; i < 8; i++) {
            float2 p = g_part[map*8 + i];
            m = fmaxf(m, p.x);
            S0 += p.y;
        }
        float Z = S0 * __expf(-m);
        sh_m = m;
        sh_invZ = 1.f / Z;
        float cut = m + fmaxf(__logf(Z * (2.0f / (float)HWs)), -4.6051702f);
        unsigned u = __float_as_uint(cut);
        unsigned ord = u ^ ((u >> 31) ? 0xFFFFFFFFu : 0x80000000u);
        sh_cutkey = ((ull)(~ord)) << 32;   // key < cutkey <=> value > cut
    }
    __syncthreads();
    ull cutkey = sh_cutkey;

#pragma unroll 4
    for (int i = tid; i < CAP; i += 512) {
        if ((i & (WSEG-1)) < bcnt[i >> 10]) {
            ull key = __ldg(cand + i);
            if (key < cutkey) atomicAdd(&hist[(int)(key >> 52)], 1);
        }
    }
    __syncthreads();
    if (tid < 256) {
        int sg = 0;
        for (int j = 0; j < 16; j++) sg += hist[tid*16 + j];
        psum[tid] = sg;
    }
    __syncthreads();
    if (tid == 0) {
        int run = 0;
        for (int t = 0; t < 256; t++) { int tmp = psum[t]; psum[t] = run; run += tmp; }
        sh_tot = run;
    }
    __syncthreads();
    int ntot = sh_tot;

    unsigned thr24 = 0;
    int T12 = 0;
    if (ntot > Kk) {
        if (tid < 256) {
            int c = psum[tid];
            int hi = 0;
            for (int j = 0; j < 16; j++) hi += hist[tid*16 + j];
            if (c < Kk && c + hi >= Kk) {
                int cc = c;
                for (int j = 0; j < 16; j++) {
                    int h = hist[tid*16 + j];
                    if (cc + h >= Kk) { sh_T = tid*16 + j; sh_C = cc; sh_H = h; break; }
                    cc += h;
                }
            }
        }
        __syncthreads();
        int T = sh_T, C0 = sh_C, HT = sh_H;
        if (C0 + HT <= 2048) {
            if (tid == 0) sh_mode = 1;
            T12 = T;
        } else {
            __syncthreads();
            for (int i = tid; i < 4096; i += 512) hist[i] = 0;
            __syncthreads();
            for (int i = tid; i < CAP; i += 512) {
                if ((i & (WSEG-1)) < bcnt[i >> 10]) {
                    ull key = __ldg(cand + i);
                    if (key < cutkey && (int)(key >> 52) == T)
                        atomicAdd(&hist[(int)((key >> 40) & 0xFFF)], 1);
                }
            }
            __syncthreads();
            int need = Kk - C0;
            if (tid < 256) {
                int sg = 0;
                for (int j = 0; j < 16; j++) sg += hist[tid*16 + j];
                psum[tid] = sg;
            }
            __syncthreads();
            if (tid == 0) { int run = 0; for (int t = 0; t < 256; t++) { int tmp = psum[t]; psum[t] = run; run += tmp; } }
            __syncthreads();
            if (tid < 256) {
                int c = psum[tid];
                int hi = 0;
                for (int j = 0; j < 16; j++) hi += hist[tid*16 + j];
                if (c < need && c + hi >= need) {
                    int cc = c;
                    for (int j = 0; j < 16; j++) {
                        int h = hist[tid*16 + j];
                        if (cc + h >= need) { sh_T = tid*16 + j; break; }
                        cc += h;
                    }
                }
            }
            if (tid == 0) sh_mode = 2;
            __syncthreads();
            thr24 = ((unsigned)T << 12) | (unsigned)sh_T;
            T12 = T;
        }
    }
    __syncthreads();
    int mode = sh_mode;

#pragma unroll 4
    for (int i = tid; i < CAP; i += 512) {
        if ((i & (WSEG-1)) < bcnt[i >> 10]) {
            ull key = __ldg(cand + i);
            if (key >= cutkey) continue;
            bool keep;
            if (mode == 0)      keep = true;
            else if (mode == 1) keep = ((int)(key >> 52) <= T12);
            else                keep = ((unsigned)(key >> 40) <= thr24);
            if (keep) {
                int p = atomicAdd(&nlist, 1);
                if (p < 2048) list[p] = key;
            }
        }
    }
    __syncthreads();
    int M = min(nlist, 2048);
    float m = sh_m;
    float invZ = sh_invZ;

    for (int t = tid; t < M; t += 512) {
        ull k = list[t];
        int rank = 0;
        for (int j = 0; j < M; j++) rank += (list[j] < k);
        if (rank < Kk) {
            unsigned idx = (unsigned)(k & 0xFFFFFFFFu);
            int gx = idx & 511, gy = idx >> 9;
            unsigned ord = ~(unsigned)(k >> 32);
            unsigned u = (ord & 0x80000000u) ? (ord ^ 0x80000000u) : ~ord;
            float v = __uint_as_float(u);
            float sc = __expf(v - m) * invZ;
            int o = map*Kk + rank;
            out[OFF_SCORES + o]       = sc;
            out[OFF_COORDS + o*2]     = (float)gx;
            out[OFF_COORDS + o*2 + 1] = (float)gy;
            out[OFF_VALID  + o]       = 1.f;
            g_selx[o] = gx; g_sely[o] = gy; g_selv[o] = 1;
        }
    }
    if (tid >= M && tid < Kk) {
        int o = map*Kk + tid;
        out[OFF_SCORES + o]       = 0.f;
        out[OFF_COORDS + o*2]     = 0.f;
        out[OFF_COORDS + o*2 + 1] = 0.f;
        out[OFF_VALID  + o]       = 0.f;
        g_selx[o] = 0; g_sely[o] = 0; g_selv[o] = 0;
    }
}

// ---------------------------------------------------------------------------
// Kernel 3: KxK pair edges. grid (40, B*A).
// ---------------------------------------------------------------------------
__global__ void __launch_bounds__(256) k_pairs(const float* __restrict__ paf,
                                               float* __restrict__ out) {
    int ba = blockIdx.y;
    int a  = ba % Aa;
    int b  = ba / Aa;
    int m1 = b*Ss + a, m2 = m1 + 1;
    __shared__ int x1[Kk], y1[Kk], v1[Kk], x2[Kk], y2[Kk], v2[Kk];
    int tid = threadIdx.x;
    if (tid < Kk) {
        x1[tid] = g_selx[m1*Kk + tid]; y1[tid] = g_sely[m1*Kk + tid]; v1[tid] = g_selv[m1*Kk + tid];
        x2[tid] = g_selx[m2*Kk + tid]; y2[tid] = g_sely[m2*Kk + tid]; v2[tid] = g_selv[m2*Kk + tid];
    }
    __syncthreads();
    int idx = blockIdx.x * 256 + tid;
    if (idx >= Kk*Kk) return;
    const float* pafx = paf + (size_t)(ba*2)*HWs;
    const float* pafy = pafx + HWs;
    size_t eb = (size_t)ba * Kk * Kk;
    size_t ib = (size_t)ba * 2 * Kk * Kk;
    int j2 = idx / Kk, j1 = idx - j2*Kk;
    float dx = (float)(x2[j2] - x1[j1]);
    float dy = (float)(y2[j2] - y1[j1]);
    float R = sqrtf(dx*dx + dy*dy);
    bool pv = (R < 20.0f) && v1[j1] && v2[j2];
    float li = 0.f;
    if (pv && R > 0.f) {
        float tvx = dx / R, tvy = dy / R;
        int px1 = x1[j1], py1 = y1[j1], px2 = x2[j2], py2 = y2[j2];
        float acc = 0.f;
#pragma unroll
        for (int t = 0; t < 10; t++) {
            int sx = (px1*(9 - t) + px2*t) / 9;
            int sy = (py1*(9 - t) + py2*t) / 9;
            int off = sy*Ww + sx;
            acc += tvx*__ldg(pafx + off) + tvy*__ldg(pafy + off);
        }
        li = acc * 0.1f;
    }
    out[OFF_EPAF + eb + idx] = li;
    out[OFF_ER   + eb + idx] = pv ? R : 0.f;
    out[OFF_PV   + eb + idx] = pv ? 1.f : 0.f;
    out[OFF_IP   + ib + idx]           = (float)(a*Kk + j1);
    out[OFF_IP   + ib + Kk*Kk + idx]   = (float)((a + 1)*Kk + j2);
}

extern "C" void kernel_launch(void* const* d_in, const int* in_sizes, int n_in,
                              void* d_out, int out_size) {
    const float* pose = (const float*)d_in[0];
    const float* paf  = (const float*)d_in[1];
    float* out = (float*)d_out;
    k_fused <<<dim3(8, NMAPS), 256>>>(pose);
    k_topk  <<<NMAPS, 512>>>(out);
    k_pairs <<<dim3((Kk*Kk + 255)/256, Bb*Aa), 256>>>(paf, out);
}